// round 16
// baseline (speedup 1.0000x reference)
#include <cuda_runtime.h>
#include <cuda_fp16.h>
#include <math.h>

#define NNODES 100000
#define NEDGES 1600000
#define INC 128
#define HID 128
#define OUTC 18
#define NB 98

// ---------------- scratch ----------------
__device__ __align__(16) float g_dinv[NNODES];
__device__ __align__(16) __half g_xh[(size_t)NNODES * INC];
__device__ __align__(16) __half g_w1h[INC * HID];
__device__ __align__(16) __half g_h1h[(size_t)NNODES * HID];
__device__ __align__(16) __half g_h2h[(size_t)NNODES * OUTC];
__device__ int g_degi[NNODES];
__device__ int g_rowstart[NNODES + 1];
__device__ int g_cursor[NNODES];
__device__ __align__(8) int2 g_cadj[NEDGES];   // {src, dinv[src] bits}
__device__ int g_bsum[128];
__device__ int g_is64;
__device__ unsigned int g_arr1;
__device__ unsigned int g_arr2;

// ---------------- K1: detect + degree count + fp16 convert ----------------
__global__ void k_prep(const void* __restrict__ ei,
                       const float* __restrict__ x, const float* __restrict__ W1) {
    __shared__ int s_is64;
    const unsigned int* eiw = (const unsigned int*)ei;
    if (threadIdx.x < 32) {
        unsigned int any = 0;
        for (int q = threadIdx.x; q < 128; q += 32) any |= eiw[2 * q + 1];
        unsigned int b = __ballot_sync(0xffffffffu, any != 0u);
        if (threadIdx.x == 0) s_is64 = (b == 0u);
    }
    __syncthreads();
    int i = blockIdx.x * blockDim.x + threadIdx.x;
    if (i == 0) g_is64 = s_is64;
    if (i < NEDGES) {
        int d = s_is64 ? (int)((const long long*)ei)[NEDGES + i]
                       : ((const int*)ei)[NEDGES + i];
        atomicAdd(&g_degi[d], 1);
    }
    if (i < NNODES * INC / 4) {
        float4 v = ((const float4*)x)[i];
        __half2 lo = __floats2half2_rn(v.x, v.y);
        __half2 hi = __floats2half2_rn(v.z, v.w);
        uint2 u;
        u.x = *(unsigned int*)&lo;
        u.y = *(unsigned int*)&hi;
        *(uint2*)(g_xh + (size_t)i * 4) = u;
    }
    if (i < INC * HID / 4) {
        float4 v = ((const float4*)W1)[i];
        __half2 lo = __floats2half2_rn(v.x, v.y);
        __half2 hi = __floats2half2_rn(v.z, v.w);
        uint2 u;
        u.x = *(unsigned int*)&lo;
        u.y = *(unsigned int*)&hi;
        *(uint2*)(g_w1h + (size_t)i * 4) = u;
    }
}

// ---------------- GEMM1 tensor cores, 512 thr, cp.async double buffer ----------------
#define XS_STRIDE 144
#define WS_STRIDE 272
#define SX_BYTES (128 * XS_STRIDE)
#define SW_BYTES (64 * WS_STRIDE)
#define PHASE_BYTES (SX_BYTES + SW_BYTES)
#define GEMM1_SMEM (2 * PHASE_BYTES)

__device__ __forceinline__ void cp16(unsigned int dst, const void* src, int srcsize) {
    asm volatile("cp.async.cg.shared.global [%0], [%1], 16, %2;"
                 :: "r"(dst), "l"(src), "r"(srcsize));
}

__global__ __launch_bounds__(512, 2) void k_gemm1_mma() {
    extern __shared__ __align__(16) unsigned char dynsmem[];
    const int tid = threadIdx.x;
    const int wid = tid >> 5;
    const int lane = tid & 31;
    const int slab = wid >> 1;
    const int half = wid & 1;
    const int row0 = blockIdx.x * 128;

#pragma unroll
    for (int kp = 0; kp < 2; kp++) {
        unsigned char* s_x = dynsmem + kp * PHASE_BYTES;
        unsigned char* s_w = s_x + SX_BYTES;
        for (int i = tid; i < 128 * 8; i += 512) {
            int r = i >> 3, c = i & 7;
            const void* src = g_xh + (size_t)(row0 + r) * INC + kp * 64 + c * 8;
            int vsz = (row0 + r < NNODES) ? 16 : 0;
            unsigned int dst = (unsigned int)__cvta_generic_to_shared(s_x + r * XS_STRIDE + c * 16);
            cp16(dst, src, vsz);
        }
        for (int i = tid; i < 64 * 16; i += 512) {
            int r = i >> 4, c = i & 15;
            const void* src = g_w1h + (size_t)(kp * 64 + r) * HID + c * 8;
            unsigned int dst = (unsigned int)__cvta_generic_to_shared(s_w + r * WS_STRIDE + c * 16);
            cp16(dst, src, 16);
        }
        asm volatile("cp.async.commit_group;");
    }

    float acc[8][4];
#pragma unroll
    for (int t = 0; t < 8; t++)
#pragma unroll
        for (int q = 0; q < 4; q++) acc[t][q] = 0.0f;

#pragma unroll
    for (int kp = 0; kp < 2; kp++) {
        if (kp == 0) asm volatile("cp.async.wait_group 1;");
        else         asm volatile("cp.async.wait_group 0;");
        __syncthreads();
        unsigned char* s_x = dynsmem + kp * PHASE_BYTES;
        unsigned char* s_w = s_x + SX_BYTES;

#pragma unroll
        for (int kk = 0; kk < 4; kk++) {
            unsigned int a0, a1, a2, a3;
            {
                const unsigned char* p = s_x + (slab * 16 + (lane & 15)) * XS_STRIDE
                                             + kk * 32 + (lane >> 4) * 16;
                unsigned int sa = (unsigned int)__cvta_generic_to_shared(p);
                asm volatile("ldmatrix.sync.aligned.m8n8.x4.shared.b16 {%0,%1,%2,%3}, [%4];"
                             : "=r"(a0), "=r"(a1), "=r"(a2), "=r"(a3) : "r"(sa));
            }
#pragma unroll
            for (int j = 0; j < 4; j++) {
                unsigned int b0, b1, b2, b3;
                const unsigned char* p = s_w + (kk * 16 + (lane & 15)) * WS_STRIDE
                                             + half * 128 + j * 32 + (lane >> 4) * 16;
                unsigned int sb = (unsigned int)__cvta_generic_to_shared(p);
                asm volatile("ldmatrix.sync.aligned.m8n8.x4.trans.shared.b16 {%0,%1,%2,%3}, [%4];"
                             : "=r"(b0), "=r"(b1), "=r"(b2), "=r"(b3) : "r"(sb));
                asm volatile("mma.sync.aligned.m16n8k16.row.col.f32.f16.f16.f32 "
                             "{%0,%1,%2,%3}, {%4,%5,%6,%7}, {%8,%9}, {%0,%1,%2,%3};"
                             : "+f"(acc[2 * j][0]), "+f"(acc[2 * j][1]),
                               "+f"(acc[2 * j][2]), "+f"(acc[2 * j][3])
                             : "r"(a0), "r"(a1), "r"(a2), "r"(a3), "r"(b0), "r"(b1));
                asm volatile("mma.sync.aligned.m16n8k16.row.col.f32.f16.f16.f32 "
                             "{%0,%1,%2,%3}, {%4,%5,%6,%7}, {%8,%9}, {%0,%1,%2,%3};"
                             : "+f"(acc[2 * j + 1][0]), "+f"(acc[2 * j + 1][1]),
                               "+f"(acc[2 * j + 1][2]), "+f"(acc[2 * j + 1][3])
                             : "r"(a0), "r"(a1), "r"(a2), "r"(a3), "r"(b2), "r"(b3));
            }
        }
        __syncthreads();
    }

    int gr = lane >> 2;
    int gc = (lane & 3) * 2;
    int r1 = row0 + slab * 16 + gr;
    int r2 = r1 + 8;
#pragma unroll
    for (int t = 0; t < 8; t++) {
        int col = half * 64 + t * 8 + gc;
        if (r1 < NNODES) {
            __half2 h = __floats2half2_rn(acc[t][0], acc[t][1]);
            *(__half2*)(g_h1h + (size_t)r1 * HID + col) = h;
        }
        if (r2 < NNODES) {
            __half2 h = __floats2half2_rn(acc[t][2], acc[t][3]);
            *(__half2*)(g_h1h + (size_t)r2 * HID + col) = h;
        }
    }
}

// ---------------- scan + dinv + CSR fill (persistent, grid barrier) ----------------
__device__ __forceinline__ void grid_barrier(unsigned int* cnt) {
    __syncthreads();
    __threadfence();
    if (threadIdx.x == 0) {
        unsigned int old = atomicAdd(cnt, 1u);
        unsigned int target = (old / NB + 1u) * NB;
        while (atomicAdd(cnt, 0u) < target) {}
    }
    __syncthreads();
}

__global__ __launch_bounds__(1024) void k_scanfill(const void* __restrict__ ei) {
    __shared__ int sh[1024];
    __shared__ int sp[128];
    const int b = blockIdx.x;
    const int t = threadIdx.x;
    const int i = b * 1024 + t;

    int deg = (i < NNODES) ? g_degi[i] : 0;
    sh[t] = deg;
    __syncthreads();
    for (int off = 1; off < 1024; off <<= 1) {
        int v = (t >= off) ? sh[t - off] : 0;
        __syncthreads();
        sh[t] += v;
        __syncthreads();
    }
    int incl = sh[t];
    if (t == 1023) g_bsum[b] = incl;

    grid_barrier(&g_arr1);

    if (t < 128) sp[t] = (t < NB) ? g_bsum[t] : 0;
    __syncthreads();
    for (int off = 1; off < 128; off <<= 1) {
        int v = (t < 128 && t >= off) ? sp[t - off] : 0;
        __syncthreads();
        if (t < 128) sp[t] += v;
        __syncthreads();
    }
    int ebase = (b == 0) ? 0 : sp[b - 1];
    if (i < NNODES) {
        int r = ebase + incl - deg;
        g_rowstart[i] = r;
        g_cursor[i] = r;
        g_dinv[i] = rsqrtf(1.0f + (float)deg);
        g_degi[i] = 0;
    }
    if (i == 0) g_rowstart[NNODES] = NEDGES;

    grid_barrier(&g_arr2);

    const int is64 = g_is64;
    const long long* p64 = (const long long*)ei;
    const int* p32 = (const int*)ei;
    for (int e = b * 1024 + t; e < NEDGES; e += NB * 1024) {
        int s, d;
        if (is64) { s = (int)p64[e]; d = (int)p64[NEDGES + e]; }
        else      { s = p32[e];      d = p32[NEDGES + e]; }
        int pos = atomicAdd(&g_cursor[d], 1);
        g_cadj[pos] = make_int2(s, __float_as_int(g_dinv[s]));
    }
}

// ---------------- Layer 1: fp16 gather (direct cadj loads) + MMA GEMM2 epilogue ----------------
#define AGH_STRIDE 272
#define W2H_STRIDE 80
__global__ __launch_bounds__(256, 5) void k_layer1(const float* __restrict__ b1,
                                                   const float* __restrict__ W2) {
    __shared__ __align__(16) unsigned char s_aggh[16 * AGH_STRIDE];
    __shared__ __align__(16) unsigned char s_w2h[128 * W2H_STRIDE];

    for (int i = threadIdx.x; i < 128 * 40 / 2; i += blockDim.x)
        ((unsigned int*)s_w2h)[i] = 0u;
    __syncthreads();
    for (int i = threadIdx.x; i < HID * OUTC; i += blockDim.x) {
        int k = i / OUTC, oc = i - k * OUTC;
        *(__half*)(s_w2h + k * W2H_STRIDE + oc * 2) = __float2half_rn(W2[i]);
    }

    const int wid = threadIdx.x >> 5;
    const int lane = threadIdx.x & 31;
    const int h = lane >> 4;
    const int hl = lane & 15;
    const int node = blockIdx.x * 16 + wid * 2 + h;

    {
        float din = g_dinv[node];
        int rs = g_rowstart[node];
        int re = g_rowstart[node + 1];
        const __half* hbase = g_h1h + hl * 8;

        uint4 us = *(const uint4*)(g_h1h + (size_t)node * HID + hl * 8);
        const __half2* up = (const __half2*)&us;
        float2 f0 = __half22float2(up[0]), f1 = __half22float2(up[1]);
        float2 f2 = __half22float2(up[2]), f3 = __half22float2(up[3]);
        float di2 = din * din;
        float4 ba = *(const float4*)(b1 + hl * 8);
        float4 bb = *(const float4*)(b1 + hl * 8 + 4);
        float4 acc0, acc1;
        acc0.x = ba.x + di2 * f0.x; acc0.y = ba.y + di2 * f0.y;
        acc0.z = ba.z + di2 * f1.x; acc0.w = ba.w + di2 * f1.y;
        acc1.x = bb.x + di2 * f2.x; acc1.y = bb.y + di2 * f2.y;
        acc1.z = bb.z + di2 * f3.x; acc1.w = bb.w + di2 * f3.y;

        int j = rs;
        for (; j + 4 <= re; j += 4) {
            uint4 u[4]; float w[4];
#pragma unroll
            for (int q = 0; q < 4; q++) {
                int2 e = g_cadj[j + q];
                w[q] = __int_as_float(e.y) * din;
                u[q] = *(const uint4*)(hbase + ((size_t)((unsigned)e.x << 7)));
            }
#pragma unroll
            for (int q = 0; q < 4; q++) {
                const __half2* vp = (const __half2*)&u[q];
                float2 a = __half22float2(vp[0]), b = __half22float2(vp[1]);
                float2 c = __half22float2(vp[2]), d = __half22float2(vp[3]);
                acc0.x = fmaf(w[q], a.x, acc0.x); acc0.y = fmaf(w[q], a.y, acc0.y);
                acc0.z = fmaf(w[q], b.x, acc0.z); acc0.w = fmaf(w[q], b.y, acc0.w);
                acc1.x = fmaf(w[q], c.x, acc1.x); acc1.y = fmaf(w[q], c.y, acc1.y);
                acc1.z = fmaf(w[q], d.x, acc1.z); acc1.w = fmaf(w[q], d.y, acc1.w);
            }
        }
        for (; j < re; j++) {
            int2 e = g_cadj[j];
            float w = __int_as_float(e.y) * din;
            uint4 u = *(const uint4*)(hbase + ((size_t)((unsigned)e.x << 7)));
            const __half2* vp = (const __half2*)&u;
            float2 a = __half22float2(vp[0]), b = __half22float2(vp[1]);
            float2 c = __half22float2(vp[2]), d = __half22float2(vp[3]);
            acc0.x = fmaf(w, a.x, acc0.x); acc0.y = fmaf(w, a.y, acc0.y);
            acc0.z = fmaf(w, b.x, acc0.z); acc0.w = fmaf(w, b.y, acc0.w);
            acc1.x = fmaf(w, c.x, acc1.x); acc1.y = fmaf(w, c.y, acc1.y);
            acc1.z = fmaf(w, d.x, acc1.z); acc1.w = fmaf(w, d.y, acc1.w);
        }

        __half2 p0 = __floats2half2_rn(fmaxf(acc0.x, 0.f), fmaxf(acc0.y, 0.f));
        __half2 p1 = __floats2half2_rn(fmaxf(acc0.z, 0.f), fmaxf(acc0.w, 0.f));
        __half2 p2 = __floats2half2_rn(fmaxf(acc1.x, 0.f), fmaxf(acc1.y, 0.f));
        __half2 p3 = __floats2half2_rn(fmaxf(acc1.z, 0.f), fmaxf(acc1.w, 0.f));
        uint4 pk;
        pk.x = *(unsigned int*)&p0; pk.y = *(unsigned int*)&p1;
        pk.z = *(unsigned int*)&p2; pk.w = *(unsigned int*)&p3;
        *(uint4*)(s_aggh + (wid * 2 + h) * AGH_STRIDE + hl * 16) = pk;
    }
    __syncthreads();

    if (wid == 0) {
        float acc[3][4];
#pragma unroll
        for (int nt = 0; nt < 3; nt++)
#pragma unroll
            for (int q = 0; q < 4; q++) acc[nt][q] = 0.0f;

#pragma unroll
        for (int kk = 0; kk < 8; kk++) {
            unsigned int a0, a1, a2, a3;
            {
                const unsigned char* p = s_aggh + (lane & 15) * AGH_STRIDE
                                               + kk * 32 + (lane >> 4) * 16;
                unsigned int sa = (unsigned int)__cvta_generic_to_shared(p);
                asm volatile("ldmatrix.sync.aligned.m8n8.x4.shared.b16 {%0,%1,%2,%3}, [%4];"
                             : "=r"(a0), "=r"(a1), "=r"(a2), "=r"(a3) : "r"(sa));
            }
            unsigned int b0, b1, b2, b3, c0, c1, c2, c3;
            {
                const unsigned char* p = s_w2h + (kk * 16 + (lane & 15)) * W2H_STRIDE
                                               + (lane >> 4) * 16;
                unsigned int sb = (unsigned int)__cvta_generic_to_shared(p);
                asm volatile("ldmatrix.sync.aligned.m8n8.x4.trans.shared.b16 {%0,%1,%2,%3}, [%4];"
                             : "=r"(b0), "=r"(b1), "=r"(b2), "=r"(b3) : "r"(sb));
                asm volatile("ldmatrix.sync.aligned.m8n8.x4.trans.shared.b16 {%0,%1,%2,%3}, [%4];"
                             : "=r"(c0), "=r"(c1), "=r"(c2), "=r"(c3) : "r"(sb + 32));
            }
            asm volatile("mma.sync.aligned.m16n8k16.row.col.f32.f16.f16.f32 "
                         "{%0,%1,%2,%3}, {%4,%5,%6,%7}, {%8,%9}, {%0,%1,%2,%3};"
                         : "+f"(acc[0][0]), "+f"(acc[0][1]), "+f"(acc[0][2]), "+f"(acc[0][3])
                         : "r"(a0), "r"(a1), "r"(a2), "r"(a3), "r"(b0), "r"(b1));
            asm volatile("mma.sync.aligned.m16n8k16.row.col.f32.f16.f16.f32 "
                         "{%0,%1,%2,%3}, {%4,%5,%6,%7}, {%8,%9}, {%0,%1,%2,%3};"
                         : "+f"(acc[1][0]), "+f"(acc[1][1]), "+f"(acc[1][2]), "+f"(acc[1][3])
                         : "r"(a0), "r"(a1), "r"(a2), "r"(a3), "r"(b2), "r"(b3));
            asm volatile("mma.sync.aligned.m16n8k16.row.col.f32.f16.f16.f32 "
                         "{%0,%1,%2,%3}, {%4,%5,%6,%7}, {%8,%9}, {%0,%1,%2,%3};"
                         : "+f"(acc[2][0]), "+f"(acc[2][1]), "+f"(acc[2][2]), "+f"(acc[2][3])
                         : "r"(a0), "r"(a1), "r"(a2), "r"(a3), "r"(c0), "r"(c1));
        }

        int gr = lane >> 2;
        int gc = (lane & 3) * 2;
        int n0 = blockIdx.x * 16 + gr;
        int n1 = n0 + 8;
#pragma unroll
        for (int nt = 0; nt < 2; nt++) {
            int c = nt * 8 + gc;
            __half2 hA = __floats2half2_rn(acc[nt][0], acc[nt][1]);
            __half2 hB = __floats2half2_rn(acc[nt][2], acc[nt][3]);
            *(__half2*)(g_h2h + (size_t)n0 * OUTC + c) = hA;
            *(__half2*)(g_h2h + (size_t)n1 * OUTC + c) = hB;
        }
        if (gc == 0) {
            __half2 hA = __floats2half2_rn(acc[2][0], acc[2][1]);
            __half2 hB = __floats2half2_rn(acc[2][2], acc[2][3]);
            *(__half2*)(g_h2h + (size_t)n0 * OUTC + 16) = hA;
            *(__half2*)(g_h2h + (size_t)n1 * OUTC + 16) = hB;
        }
    }
}

// ---------------- Layer 2: 2 nodes/warp, direct cadj loads, log_softmax ----------------
__global__ __launch_bounds__(256) void k_layer2(const float* __restrict__ b2,
                                                float* __restrict__ out) {
    const int wid = threadIdx.x >> 5;
    const int lane = threadIdx.x & 31;
    const int h = lane >> 4;
    const int hl = lane & 15;
    const unsigned hmask = h ? 0xffff0000u : 0x0000ffffu;
    const int node = blockIdx.x * 16 + wid * 2 + h;
    if (node >= NNODES) return;

    float din = g_dinv[node];
    int rs = g_rowstart[node];
    int re = g_rowstart[node + 1];

    float2 acc = make_float2(0.f, 0.f);
    if (hl < 9) {
        __half2 hv = *(const __half2*)(g_h2h + (size_t)node * OUTC + 2 * hl);
        float2 f = __half22float2(hv);
        float di2 = din * din;
        acc.x = b2[2 * hl]     + di2 * f.x;
        acc.y = b2[2 * hl + 1] + di2 * f.y;
    }

    int j = rs;
    for (; j + 4 <= re; j += 4) {
        float2 v[4]; float w[4];
#pragma unroll
        for (int q = 0; q < 4; q++) {
            int2 e = g_cadj[j + q];
            w[q] = __int_as_float(e.y) * din;
            v[q] = make_float2(0.f, 0.f);
            if (hl < 9)
                v[q] = __half22float2(*(const __half2*)(g_h2h + (size_t)e.x * OUTC + 2 * hl));
        }
#pragma unroll
        for (int q = 0; q < 4; q++) {
            acc.x = fmaf(w[q], v[q].x, acc.x);
            acc.y = fmaf(w[q], v[q].y, acc.y);
        }
    }
    for (; j < re; j++) {
        int2 e = g_cadj[j];
        float w = __int_as_float(e.y) * din;
        if (hl < 9) {
            float2 v = __half22float2(*(const __half2*)(g_h2h + (size_t)e.x * OUTC + 2 * hl));
            acc.x = fmaf(w, v.x, acc.x);
            acc.y = fmaf(w, v.y, acc.y);
        }
    }

    float m = (hl < 9) ? fmaxf(acc.x, acc.y) : -1e30f;
#pragma unroll
    for (int off = 8; off; off >>= 1)
        m = fmaxf(m, __shfl_xor_sync(hmask, m, off));
    float e = (hl < 9) ? (expf(acc.x - m) + expf(acc.y - m)) : 0.f;
#pragma unroll
    for (int off = 8; off; off >>= 1)
        e += __shfl_xor_sync(hmask, e, off);
    float ls = m + logf(e);
    if (hl < 9) {
        float2 o = make_float2(acc.x - ls, acc.y - ls);
        *(float2*)(out + (size_t)node * OUTC + 2 * hl) = o;
    }
}

// ---------------- launch (stream-fork overlap of gemm1 and scanfill) ----------------
extern "C" void kernel_launch(void* const* d_in, const int* in_sizes, int n_in,
                              void* d_out, int out_size) {
    const float* x = 0; const void* ei = 0;
    const float* W1 = 0; const float* b1 = 0;
    const float* W2 = 0; const float* b2 = 0;
    for (int i = 0; i < n_in; i++) {
        long long sz = in_sizes[i];
        if (sz == (long long)NNODES * INC) x = (const float*)d_in[i];
        else if (sz == 2LL * NEDGES)       ei = d_in[i];
        else if (sz == (long long)INC * HID) W1 = (const float*)d_in[i];
        else if (sz == HID)                b1 = (const float*)d_in[i];
        else if (sz == (long long)HID * OUTC) W2 = (const float*)d_in[i];
        else if (sz == OUTC)               b2 = (const float*)d_in[i];
    }
    float* out = (float*)d_out;

    static cudaStream_t s2 = 0;
    static cudaEvent_t evA = 0, evB = 0;
    static int inited = 0;
    if (!inited) {
        cudaStreamCreateWithFlags(&s2, cudaStreamNonBlocking);
        cudaEventCreateWithFlags(&evA, cudaEventDisableTiming);
        cudaEventCreateWithFlags(&evB, cudaEventDisableTiming);
        cudaFuncSetAttribute(k_gemm1_mma, cudaFuncAttributeMaxDynamicSharedMemorySize, GEMM1_SMEM);
        inited = 1;
    }

    k_prep<<<(NNODES * INC / 4 + 255) / 256, 256>>>(ei, x, W1);

    // fork: gemm1 on s2, scanfill on main (independent after prep)
    cudaEventRecord(evA, 0);
    cudaStreamWaitEvent(s2, evA, 0);
    k_gemm1_mma<<<(NNODES + 127) / 128, 512, GEMM1_SMEM, s2>>>();
    cudaEventRecord(evB, s2);

    k_scanfill<<<NB, 1024>>>(ei);

    // join
    cudaStreamWaitEvent(0, evB, 0);

    k_layer1<<<NNODES / 16, 256>>>(b1, W2);
    {
        long long thr = (long long)NNODES * 16;
        k_layer2<<<(unsigned)((thr + 255) / 256), 256>>>(b2, out);
    }
}

// round 17
// speedup vs baseline: 1.0126x; 1.0126x over previous
#include <cuda_runtime.h>
#include <cuda_fp16.h>
#include <math.h>

#define NNODES 100000
#define NEDGES 1600000
#define INC 128
#define HID 128
#define OUTC 18
#define NB 98

// ---------------- scratch ----------------
__device__ __align__(16) float g_dinv[NNODES];
__device__ __align__(16) __half g_xh[(size_t)NNODES * INC];
__device__ __align__(16) __half g_w1h[INC * HID];
__device__ __align__(16) __half g_h1h[(size_t)NNODES * HID];
__device__ __align__(16) __half g_h2h[(size_t)NNODES * OUTC];
__device__ int g_degi[NNODES];
__device__ int g_rowstart[NNODES + 1];
__device__ int g_cursor[NNODES];
__device__ __align__(8) int2 g_cadj[NEDGES];   // {src, dinv[src] bits}
__device__ int g_bsum[128];
__device__ int g_is64;
__device__ unsigned int g_arr1;
__device__ unsigned int g_arr2;

// ---------------- K1: detect + degree count + fp16 convert ----------------
__global__ void k_prep(const void* __restrict__ ei,
                       const float* __restrict__ x, const float* __restrict__ W1) {
    __shared__ int s_is64;
    const unsigned int* eiw = (const unsigned int*)ei;
    if (threadIdx.x < 32) {
        unsigned int any = 0;
        for (int q = threadIdx.x; q < 128; q += 32) any |= eiw[2 * q + 1];
        unsigned int b = __ballot_sync(0xffffffffu, any != 0u);
        if (threadIdx.x == 0) s_is64 = (b == 0u);
    }
    __syncthreads();
    int i = blockIdx.x * blockDim.x + threadIdx.x;
    if (i == 0) g_is64 = s_is64;
    if (i < NEDGES) {
        int d = s_is64 ? (int)((const long long*)ei)[NEDGES + i]
                       : ((const int*)ei)[NEDGES + i];
        atomicAdd(&g_degi[d], 1);
    }
    if (i < NNODES * INC / 4) {
        float4 v = ((const float4*)x)[i];
        __half2 lo = __floats2half2_rn(v.x, v.y);
        __half2 hi = __floats2half2_rn(v.z, v.w);
        uint2 u;
        u.x = *(unsigned int*)&lo;
        u.y = *(unsigned int*)&hi;
        *(uint2*)(g_xh + (size_t)i * 4) = u;
    }
    if (i < INC * HID / 4) {
        float4 v = ((const float4*)W1)[i];
        __half2 lo = __floats2half2_rn(v.x, v.y);
        __half2 hi = __floats2half2_rn(v.z, v.w);
        uint2 u;
        u.x = *(unsigned int*)&lo;
        u.y = *(unsigned int*)&hi;
        *(uint2*)(g_w1h + (size_t)i * 4) = u;
    }
}

// ---------------- GEMM1 tensor cores, 512 thr, cp.async double buffer ----------------
#define XS_STRIDE 144
#define WS_STRIDE 272
#define SX_BYTES (128 * XS_STRIDE)
#define SW_BYTES (64 * WS_STRIDE)
#define PHASE_BYTES (SX_BYTES + SW_BYTES)
#define GEMM1_SMEM (2 * PHASE_BYTES)

__device__ __forceinline__ void cp16(unsigned int dst, const void* src, int srcsize) {
    asm volatile("cp.async.cg.shared.global [%0], [%1], 16, %2;"
                 :: "r"(dst), "l"(src), "r"(srcsize));
}

__global__ __launch_bounds__(512, 2) void k_gemm1_mma() {
    extern __shared__ __align__(16) unsigned char dynsmem[];
    const int tid = threadIdx.x;
    const int wid = tid >> 5;
    const int lane = tid & 31;
    const int slab = wid >> 1;
    const int half = wid & 1;
    const int row0 = blockIdx.x * 128;

#pragma unroll
    for (int kp = 0; kp < 2; kp++) {
        unsigned char* s_x = dynsmem + kp * PHASE_BYTES;
        unsigned char* s_w = s_x + SX_BYTES;
        for (int i = tid; i < 128 * 8; i += 512) {
            int r = i >> 3, c = i & 7;
            const void* src = g_xh + (size_t)(row0 + r) * INC + kp * 64 + c * 8;
            int vsz = (row0 + r < NNODES) ? 16 : 0;
            unsigned int dst = (unsigned int)__cvta_generic_to_shared(s_x + r * XS_STRIDE + c * 16);
            cp16(dst, src, vsz);
        }
        for (int i = tid; i < 64 * 16; i += 512) {
            int r = i >> 4, c = i & 15;
            const void* src = g_w1h + (size_t)(kp * 64 + r) * HID + c * 8;
            unsigned int dst = (unsigned int)__cvta_generic_to_shared(s_w + r * WS_STRIDE + c * 16);
            cp16(dst, src, 16);
        }
        asm volatile("cp.async.commit_group;");
    }

    float acc[8][4];
#pragma unroll
    for (int t = 0; t < 8; t++)
#pragma unroll
        for (int q = 0; q < 4; q++) acc[t][q] = 0.0f;

#pragma unroll
    for (int kp = 0; kp < 2; kp++) {
        if (kp == 0) asm volatile("cp.async.wait_group 1;");
        else         asm volatile("cp.async.wait_group 0;");
        __syncthreads();
        unsigned char* s_x = dynsmem + kp * PHASE_BYTES;
        unsigned char* s_w = s_x + SX_BYTES;

#pragma unroll
        for (int kk = 0; kk < 4; kk++) {
            unsigned int a0, a1, a2, a3;
            {
                const unsigned char* p = s_x + (slab * 16 + (lane & 15)) * XS_STRIDE
                                             + kk * 32 + (lane >> 4) * 16;
                unsigned int sa = (unsigned int)__cvta_generic_to_shared(p);
                asm volatile("ldmatrix.sync.aligned.m8n8.x4.shared.b16 {%0,%1,%2,%3}, [%4];"
                             : "=r"(a0), "=r"(a1), "=r"(a2), "=r"(a3) : "r"(sa));
            }
#pragma unroll
            for (int j = 0; j < 4; j++) {
                unsigned int b0, b1, b2, b3;
                const unsigned char* p = s_w + (kk * 16 + (lane & 15)) * WS_STRIDE
                                             + half * 128 + j * 32 + (lane >> 4) * 16;
                unsigned int sb = (unsigned int)__cvta_generic_to_shared(p);
                asm volatile("ldmatrix.sync.aligned.m8n8.x4.trans.shared.b16 {%0,%1,%2,%3}, [%4];"
                             : "=r"(b0), "=r"(b1), "=r"(b2), "=r"(b3) : "r"(sb));
                asm volatile("mma.sync.aligned.m16n8k16.row.col.f32.f16.f16.f32 "
                             "{%0,%1,%2,%3}, {%4,%5,%6,%7}, {%8,%9}, {%0,%1,%2,%3};"
                             : "+f"(acc[2 * j][0]), "+f"(acc[2 * j][1]),
                               "+f"(acc[2 * j][2]), "+f"(acc[2 * j][3])
                             : "r"(a0), "r"(a1), "r"(a2), "r"(a3), "r"(b0), "r"(b1));
                asm volatile("mma.sync.aligned.m16n8k16.row.col.f32.f16.f16.f32 "
                             "{%0,%1,%2,%3}, {%4,%5,%6,%7}, {%8,%9}, {%0,%1,%2,%3};"
                             : "+f"(acc[2 * j + 1][0]), "+f"(acc[2 * j + 1][1]),
                               "+f"(acc[2 * j + 1][2]), "+f"(acc[2 * j + 1][3])
                             : "r"(a0), "r"(a1), "r"(a2), "r"(a3), "r"(b2), "r"(b3));
            }
        }
        __syncthreads();
    }

    int gr = lane >> 2;
    int gc = (lane & 3) * 2;
    int r1 = row0 + slab * 16 + gr;
    int r2 = r1 + 8;
#pragma unroll
    for (int t = 0; t < 8; t++) {
        int col = half * 64 + t * 8 + gc;
        if (r1 < NNODES) {
            __half2 h = __floats2half2_rn(acc[t][0], acc[t][1]);
            *(__half2*)(g_h1h + (size_t)r1 * HID + col) = h;
        }
        if (r2 < NNODES) {
            __half2 h = __floats2half2_rn(acc[t][2], acc[t][3]);
            *(__half2*)(g_h1h + (size_t)r2 * HID + col) = h;
        }
    }
}

// ---------------- scan + dinv + CSR fill (persistent, grid barrier) ----------------
__device__ __forceinline__ void grid_barrier(unsigned int* cnt) {
    __syncthreads();
    __threadfence();
    if (threadIdx.x == 0) {
        unsigned int old = atomicAdd(cnt, 1u);
        unsigned int target = (old / NB + 1u) * NB;
        while (atomicAdd(cnt, 0u) < target) {}
    }
    __syncthreads();
}

__global__ __launch_bounds__(1024) void k_scanfill(const void* __restrict__ ei) {
    __shared__ int sh[1024];
    __shared__ int sp[128];
    const int b = blockIdx.x;
    const int t = threadIdx.x;
    const int i = b * 1024 + t;

    int deg = (i < NNODES) ? g_degi[i] : 0;
    sh[t] = deg;
    __syncthreads();
    for (int off = 1; off < 1024; off <<= 1) {
        int v = (t >= off) ? sh[t - off] : 0;
        __syncthreads();
        sh[t] += v;
        __syncthreads();
    }
    int incl = sh[t];
    if (t == 1023) g_bsum[b] = incl;

    grid_barrier(&g_arr1);

    if (t < 128) sp[t] = (t < NB) ? g_bsum[t] : 0;
    __syncthreads();
    for (int off = 1; off < 128; off <<= 1) {
        int v = (t < 128 && t >= off) ? sp[t - off] : 0;
        __syncthreads();
        if (t < 128) sp[t] += v;
        __syncthreads();
    }
    int ebase = (b == 0) ? 0 : sp[b - 1];
    if (i < NNODES) {
        int r = ebase + incl - deg;
        g_rowstart[i] = r;
        g_cursor[i] = r;
        g_dinv[i] = rsqrtf(1.0f + (float)deg);
        g_degi[i] = 0;
    }
    if (i == 0) g_rowstart[NNODES] = NEDGES;

    grid_barrier(&g_arr2);

    const int is64 = g_is64;
    const long long* p64 = (const long long*)ei;
    const int* p32 = (const int*)ei;
    for (int e = b * 1024 + t; e < NEDGES; e += NB * 1024) {
        int s, d;
        if (is64) { s = (int)p64[e]; d = (int)p64[NEDGES + e]; }
        else      { s = p32[e];      d = p32[NEDGES + e]; }
        int pos = atomicAdd(&g_cursor[d], 1);
        g_cadj[pos] = make_int2(s, __float_as_int(g_dinv[s]));
    }
}

// ---------------- Layer 1: pipelined fp16 gather + MMA GEMM2 epilogue ----------------
#define AGH_STRIDE 272
#define W2H_STRIDE 80
__global__ __launch_bounds__(256, 5) void k_layer1(const float* __restrict__ b1,
                                                   const float* __restrict__ W2) {
    __shared__ __align__(16) unsigned char s_aggh[16 * AGH_STRIDE];
    __shared__ __align__(16) unsigned char s_w2h[128 * W2H_STRIDE];

    for (int i = threadIdx.x; i < 128 * 40 / 2; i += blockDim.x)
        ((unsigned int*)s_w2h)[i] = 0u;
    __syncthreads();
    for (int i = threadIdx.x; i < HID * OUTC; i += blockDim.x) {
        int k = i / OUTC, oc = i - k * OUTC;
        *(__half*)(s_w2h + k * W2H_STRIDE + oc * 2) = __float2half_rn(W2[i]);
    }

    const int wid = threadIdx.x >> 5;
    const int lane = threadIdx.x & 31;
    const int h = lane >> 4;
    const int hl = lane & 15;
    const int node = blockIdx.x * 16 + wid * 2 + h;

    {
        float din = g_dinv[node];
        int rs = g_rowstart[node];
        int re = g_rowstart[node + 1];

        uint4 us = *(const uint4*)(g_h1h + (size_t)node * HID + hl * 8);
        const __half2* up = (const __half2*)&us;
        float2 f0 = __half22float2(up[0]), f1 = __half22float2(up[1]);
        float2 f2 = __half22float2(up[2]), f3 = __half22float2(up[3]);
        float di2 = din * din;
        float4 ba = *(const float4*)(b1 + hl * 8);
        float4 bb = *(const float4*)(b1 + hl * 8 + 4);
        float4 acc0, acc1;
        acc0.x = ba.x + di2 * f0.x; acc0.y = ba.y + di2 * f0.y;
        acc0.z = ba.z + di2 * f1.x; acc0.w = ba.w + di2 * f1.y;
        acc1.x = bb.x + di2 * f2.x; acc1.y = bb.y + di2 * f2.y;
        acc1.z = bb.z + di2 * f3.x; acc1.w = bb.w + di2 * f3.y;

        int j = rs;
        int2 e0, e1, e2, e3;
        if (j + 4 <= re) {
            e0 = g_cadj[j]; e1 = g_cadj[j + 1];
            e2 = g_cadj[j + 2]; e3 = g_cadj[j + 3];
        }
        // pipelined main loop: current block's gathers + FMAs overlap with next cadj prefetch
        for (; j + 8 <= re; j += 4) {
            float w0 = __int_as_float(e0.y) * din;
            float w1 = __int_as_float(e1.y) * din;
            float w2 = __int_as_float(e2.y) * din;
            float w3 = __int_as_float(e3.y) * din;
            uint4 u0 = *(const uint4*)(g_h1h + (size_t)e0.x * HID + hl * 8);
            uint4 u1 = *(const uint4*)(g_h1h + (size_t)e1.x * HID + hl * 8);
            uint4 u2 = *(const uint4*)(g_h1h + (size_t)e2.x * HID + hl * 8);
            uint4 u3 = *(const uint4*)(g_h1h + (size_t)e3.x * HID + hl * 8);
            // prefetch next 4 cadj entries (latency hidden under FMAs below)
            e0 = g_cadj[j + 4]; e1 = g_cadj[j + 5];
            e2 = g_cadj[j + 6]; e3 = g_cadj[j + 7];
            {
                const __half2* vp = (const __half2*)&u0;
                float2 a = __half22float2(vp[0]), b = __half22float2(vp[1]);
                float2 c = __half22float2(vp[2]), d = __half22float2(vp[3]);
                acc0.x = fmaf(w0, a.x, acc0.x); acc0.y = fmaf(w0, a.y, acc0.y);
                acc0.z = fmaf(w0, b.x, acc0.z); acc0.w = fmaf(w0, b.y, acc0.w);
                acc1.x = fmaf(w0, c.x, acc1.x); acc1.y = fmaf(w0, c.y, acc1.y);
                acc1.z = fmaf(w0, d.x, acc1.z); acc1.w = fmaf(w0, d.y, acc1.w);
            }
            {
                const __half2* vp = (const __half2*)&u1;
                float2 a = __half22float2(vp[0]), b = __half22float2(vp[1]);
                float2 c = __half22float2(vp[2]), d = __half22float2(vp[3]);
                acc0.x = fmaf(w1, a.x, acc0.x); acc0.y = fmaf(w1, a.y, acc0.y);
                acc0.z = fmaf(w1, b.x, acc0.z); acc0.w = fmaf(w1, b.y, acc0.w);
                acc1.x = fmaf(w1, c.x, acc1.x); acc1.y = fmaf(w1, c.y, acc1.y);
                acc1.z = fmaf(w1, d.x, acc1.z); acc1.w = fmaf(w1, d.y, acc1.w);
            }
            {
                const __half2* vp = (const __half2*)&u2;
                float2 a = __half22float2(vp[0]), b = __half22float2(vp[1]);
                float2 c = __half22float2(vp[2]), d = __half22float2(vp[3]);
                acc0.x = fmaf(w2, a.x, acc0.x); acc0.y = fmaf(w2, a.y, acc0.y);
                acc0.z = fmaf(w2, b.x, acc0.z); acc0.w = fmaf(w2, b.y, acc0.w);
                acc1.x = fmaf(w2, c.x, acc1.x); acc1.y = fmaf(w2, c.y, acc1.y);
                acc1.z = fmaf(w2, d.x, acc1.z); acc1.w = fmaf(w2, d.y, acc1.w);
            }
            {
                const __half2* vp = (const __half2*)&u3;
                float2 a = __half22float2(vp[0]), b = __half22float2(vp[1]);
                float2 c = __half22float2(vp[2]), d = __half22float2(vp[3]);
                acc0.x = fmaf(w3, a.x, acc0.x); acc0.y = fmaf(w3, a.y, acc0.y);
                acc0.z = fmaf(w3, b.x, acc0.z); acc0.w = fmaf(w3, b.y, acc0.w);
                acc1.x = fmaf(w3, c.x, acc1.x); acc1.y = fmaf(w3, c.y, acc1.y);
                acc1.z = fmaf(w3, d.x, acc1.z); acc1.w = fmaf(w3, d.y, acc1.w);
            }
        }
        // drain
        for (; j < re; j++) {
            int2 e = g_cadj[j];
            float w = __int_as_float(e.y) * din;
            uint4 u = *(const uint4*)(g_h1h + (size_t)e.x * HID + hl * 8);
            const __half2* vp = (const __half2*)&u;
            float2 a = __half22float2(vp[0]), b = __half22float2(vp[1]);
            float2 c = __half22float2(vp[2]), d = __half22float2(vp[3]);
            acc0.x = fmaf(w, a.x, acc0.x); acc0.y = fmaf(w, a.y, acc0.y);
            acc0.z = fmaf(w, b.x, acc0.z); acc0.w = fmaf(w, b.y, acc0.w);
            acc1.x = fmaf(w, c.x, acc1.x); acc1.y = fmaf(w, c.y, acc1.y);
            acc1.z = fmaf(w, d.x, acc1.z); acc1.w = fmaf(w, d.y, acc1.w);
        }

        __half2 p0 = __floats2half2_rn(fmaxf(acc0.x, 0.f), fmaxf(acc0.y, 0.f));
        __half2 p1 = __floats2half2_rn(fmaxf(acc0.z, 0.f), fmaxf(acc0.w, 0.f));
        __half2 p2 = __floats2half2_rn(fmaxf(acc1.x, 0.f), fmaxf(acc1.y, 0.f));
        __half2 p3 = __floats2half2_rn(fmaxf(acc1.z, 0.f), fmaxf(acc1.w, 0.f));
        uint4 pk;
        pk.x = *(unsigned int*)&p0; pk.y = *(unsigned int*)&p1;
        pk.z = *(unsigned int*)&p2; pk.w = *(unsigned int*)&p3;
        *(uint4*)(s_aggh + (wid * 2 + h) * AGH_STRIDE + hl * 16) = pk;
    }
    __syncthreads();

    if (wid == 0) {
        float acc[3][4];
#pragma unroll
        for (int nt = 0; nt < 3; nt++)
#pragma unroll
            for (int q = 0; q < 4; q++) acc[nt][q] = 0.0f;

#pragma unroll
        for (int kk = 0; kk < 8; kk++) {
            unsigned int a0, a1, a2, a3;
            {
                const unsigned char* p = s_aggh + (lane & 15) * AGH_STRIDE
                                               + kk * 32 + (lane >> 4) * 16;
                unsigned int sa = (unsigned int)__cvta_generic_to_shared(p);
                asm volatile("ldmatrix.sync.aligned.m8n8.x4.shared.b16 {%0,%1,%2,%3}, [%4];"
                             : "=r"(a0), "=r"(a1), "=r"(a2), "=r"(a3) : "r"(sa));
            }
            unsigned int b0, b1, b2, b3, c0, c1, c2, c3;
            {
                const unsigned char* p = s_w2h + (kk * 16 + (lane & 15)) * W2H_STRIDE
                                               + (lane >> 4) * 16;
                unsigned int sb = (unsigned int)__cvta_generic_to_shared(p);
                asm volatile("ldmatrix.sync.aligned.m8n8.x4.trans.shared.b16 {%0,%1,%2,%3}, [%4];"
                             : "=r"(b0), "=r"(b1), "=r"(b2), "=r"(b3) : "r"(sb));
                asm volatile("ldmatrix.sync.aligned.m8n8.x4.trans.shared.b16 {%0,%1,%2,%3}, [%4];"
                             : "=r"(c0), "=r"(c1), "=r"(c2), "=r"(c3) : "r"(sb + 32));
            }
            asm volatile("mma.sync.aligned.m16n8k16.row.col.f32.f16.f16.f32 "
                         "{%0,%1,%2,%3}, {%4,%5,%6,%7}, {%8,%9}, {%0,%1,%2,%3};"
                         : "+f"(acc[0][0]), "+f"(acc[0][1]), "+f"(acc[0][2]), "+f"(acc[0][3])
                         : "r"(a0), "r"(a1), "r"(a2), "r"(a3), "r"(b0), "r"(b1));
            asm volatile("mma.sync.aligned.m16n8k16.row.col.f32.f16.f16.f32 "
                         "{%0,%1,%2,%3}, {%4,%5,%6,%7}, {%8,%9}, {%0,%1,%2,%3};"
                         : "+f"(acc[1][0]), "+f"(acc[1][1]), "+f"(acc[1][2]), "+f"(acc[1][3])
                         : "r"(a0), "r"(a1), "r"(a2), "r"(a3), "r"(b2), "r"(b3));
            asm volatile("mma.sync.aligned.m16n8k16.row.col.f32.f16.f16.f32 "
                         "{%0,%1,%2,%3}, {%4,%5,%6,%7}, {%8,%9}, {%0,%1,%2,%3};"
                         : "+f"(acc[2][0]), "+f"(acc[2][1]), "+f"(acc[2][2]), "+f"(acc[2][3])
                         : "r"(a0), "r"(a1), "r"(a2), "r"(a3), "r"(c0), "r"(c1));
        }

        int gr = lane >> 2;
        int gc = (lane & 3) * 2;
        int n0 = blockIdx.x * 16 + gr;
        int n1 = n0 + 8;
#pragma unroll
        for (int nt = 0; nt < 2; nt++) {
            int c = nt * 8 + gc;
            __half2 hA = __floats2half2_rn(acc[nt][0], acc[nt][1]);
            __half2 hB = __floats2half2_rn(acc[nt][2], acc[nt][3]);
            *(__half2*)(g_h2h + (size_t)n0 * OUTC + c) = hA;
            *(__half2*)(g_h2h + (size_t)n1 * OUTC + c) = hB;
        }
        if (gc == 0) {
            __half2 hA = __floats2half2_rn(acc[2][0], acc[2][1]);
            __half2 hB = __floats2half2_rn(acc[2][2], acc[2][3]);
            *(__half2*)(g_h2h + (size_t)n0 * OUTC + 16) = hA;
            *(__half2*)(g_h2h + (size_t)n1 * OUTC + 16) = hB;
        }
    }
}

// ---------------- Layer 2: pipelined gathers, log_softmax ----------------
__global__ __launch_bounds__(256) void k_layer2(const float* __restrict__ b2,
                                                float* __restrict__ out) {
    const int wid = threadIdx.x >> 5;
    const int lane = threadIdx.x & 31;
    const int h = lane >> 4;
    const int hl = lane & 15;
    const unsigned hmask = h ? 0xffff0000u : 0x0000ffffu;
    const int node = blockIdx.x * 16 + wid * 2 + h;
    if (node >= NNODES) return;

    float din = g_dinv[node];
    int rs = g_rowstart[node];
    int re = g_rowstart[node + 1];

    float2 acc = make_float2(0.f, 0.f);
    if (hl < 9) {
        __half2 hv = *(const __half2*)(g_h2h + (size_t)node * OUTC + 2 * hl);
        float2 f = __half22float2(hv);
        float di2 = din * din;
        acc.x = b2[2 * hl]     + di2 * f.x;
        acc.y = b2[2 * hl + 1] + di2 * f.y;
    }

    int j = rs;
    int2 e0, e1, e2, e3;
    if (j + 4 <= re) {
        e0 = g_cadj[j]; e1 = g_cadj[j + 1];
        e2 = g_cadj[j + 2]; e3 = g_cadj[j + 3];
    }
    for (; j + 8 <= re; j += 4) {
        float w0 = __int_as_float(e0.y) * din;
        float w1 = __int_as_float(e1.y) * din;
        float w2 = __int_as_float(e2.y) * din;
        float w3 = __int_as_float(e3.y) * din;
        float2 v0 = make_float2(0.f, 0.f), v1 = v0, v2 = v0, v3 = v0;
        if (hl < 9) {
            v0 = __half22float2(*(const __half2*)(g_h2h + (size_t)e0.x * OUTC + 2 * hl));
            v1 = __half22float2(*(const __half2*)(g_h2h + (size_t)e1.x * OUTC + 2 * hl));
            v2 = __half22float2(*(const __half2*)(g_h2h + (size_t)e2.x * OUTC + 2 * hl));
            v3 = __half22float2(*(const __half2*)(g_h2h + (size_t)e3.x * OUTC + 2 * hl));
        }
        e0 = g_cadj[j + 4]; e1 = g_cadj[j + 5];
        e2 = g_cadj[j + 6]; e3 = g_cadj[j + 7];
        acc.x = fmaf(w0, v0.x, acc.x); acc.y = fmaf(w0, v0.y, acc.y);
        acc.x = fmaf(w1, v1.x, acc.x); acc.y = fmaf(w1, v1.y, acc.y);
        acc.x = fmaf(w2, v2.x, acc.x); acc.y = fmaf(w2, v2.y, acc.y);
        acc.x = fmaf(w3, v3.x, acc.x); acc.y = fmaf(w3, v3.y, acc.y);
    }
    for (; j < re; j++) {
        int2 e = g_cadj[j];
        float w = __int_as_float(e.y) * din;
        if (hl < 9) {
            float2 v = __half22float2(*(const __half2*)(g_h2h + (size_t)e.x * OUTC + 2 * hl));
            acc.x = fmaf(w, v.x, acc.x);
            acc.y = fmaf(w, v.y, acc.y);
        }
    }

    float m = (hl < 9) ? fmaxf(acc.x, acc.y) : -1e30f;
#pragma unroll
    for (int off = 8; off; off >>= 1)
        m = fmaxf(m, __shfl_xor_sync(hmask, m, off));
    float e = (hl < 9) ? (expf(acc.x - m) + expf(acc.y - m)) : 0.f;
#pragma unroll
    for (int off = 8; off; off >>= 1)
        e += __shfl_xor_sync(hmask, e, off);
    float ls = m + logf(e);
    if (hl < 9) {
        float2 o = make_float2(acc.x - ls, acc.y - ls);
        *(float2*)(out + (size_t)node * OUTC + 2 * hl) = o;
    }
}

// ---------------- launch (serial; fork reverted) ----------------
extern "C" void kernel_launch(void* const* d_in, const int* in_sizes, int n_in,
                              void* d_out, int out_size) {
    const float* x = 0; const void* ei = 0;
    const float* W1 = 0; const float* b1 = 0;
    const float* W2 = 0; const float* b2 = 0;
    for (int i = 0; i < n_in; i++) {
        long long sz = in_sizes[i];
        if (sz == (long long)NNODES * INC) x = (const float*)d_in[i];
        else if (sz == 2LL * NEDGES)       ei = d_in[i];
        else if (sz == (long long)INC * HID) W1 = (const float*)d_in[i];
        else if (sz == HID)                b1 = (const float*)d_in[i];
        else if (sz == (long long)HID * OUTC) W2 = (const float*)d_in[i];
        else if (sz == OUTC)               b2 = (const float*)d_in[i];
    }
    float* out = (float*)d_out;

    cudaFuncSetAttribute(k_gemm1_mma, cudaFuncAttributeMaxDynamicSharedMemorySize, GEMM1_SMEM);

    k_prep<<<(NNODES * INC / 4 + 255) / 256, 256>>>(ei, x, W1);                      // 1
    k_gemm1_mma<<<(NNODES + 127) / 128, 512, GEMM1_SMEM>>>();                        // 2
    k_scanfill<<<NB, 1024>>>(ei);                                                    // 3
    k_layer1<<<NNODES / 16, 256>>>(b1, W2);                                          // 4 (profiled)
    {
        long long thr = (long long)NNODES * 16;
        k_layer2<<<(unsigned)((thr + 255) / 256), 256>>>(b2, out);                   // 5
    }
}